// round 9
// baseline (speedup 1.0000x reference)
#include <cuda_runtime.h>
#include <cstdint>

// Problem constants
#define NUM_VERTS 6890
#define NUM_FACES 13776
#define IMG_H 1024
#define IMG_W 1024
#define NBATCH 16
#define HW (IMG_H * IMG_W)
#define PLANE_FLOATS (HW * 3)            // 3,145,728 floats per batch plane
#define THREADS 256
#define TILE_PX 1024                     // pixels per block
#define SEG_FLOATS (TILE_PX * 3)         // 3072 floats = 12KB
#define WARP_PX 128                      // pixels per warp (8 warps/block)
#define ITERS (WARP_PX / 8)              // 16: warp covers 8 px/iter (quad mapping)

// Precomputed per-face vertex attributes, 64B rows:
// row f = { v0.xyz _, v1.xyz _, v2.xyz _, ZERO-PAD }. 882KB -> L2-resident.
// The zero pad lets lane r=3 of each quad gather slot 3 harmlessly (w=0).
__device__ __align__(64) float4 g_face_attr[NUM_FACES][4];

// Kernel A: build face-attr table from batch-0 vertices (the reference's
// pixel gather never applies a per-batch face offset and batch-0 vertex
// offset is 0, so only batch 0 matters).
__global__ void __launch_bounds__(256) build_face_attr(
    const float* __restrict__ verts,   // (N, V, 3) f32
    const int*   __restrict__ faces)   // (F, 3) i32
{
    const int f = blockIdx.x * blockDim.x + threadIdx.x;
    if (f >= NUM_FACES) return;
    const int i0 = faces[f * 3 + 0];
    const int i1 = faces[f * 3 + 1];
    const int i2 = faces[f * 3 + 2];
    const float* v0 = verts + (size_t)i0 * 3;
    const float* v1 = verts + (size_t)i1 * 3;
    const float* v2 = verts + (size_t)i2 * 3;
    g_face_attr[f][0] = make_float4(v0[0], v0[1], v0[2], 0.0f);
    g_face_attr[f][1] = make_float4(v1[0], v1[1], v1[2], 0.0f);
    g_face_attr[f][2] = make_float4(v2[0], v2[1], v2[2], 0.0f);
    g_face_attr[f][3] = make_float4(0.0f, 0.0f, 0.0f, 0.0f);  // pad for lane 3
}

// Kernel B: quad-cooperative gather + interpolate into a 12KB smem segment,
// then broadcast to all 16 batch planes with coalesced streaming stores.
__global__ void __launch_bounds__(THREADS) render_kernel(
    const int*   __restrict__ pix,     // (H*W) i32
    const float* __restrict__ bary,    // (H*W, 3) f32
    float* __restrict__ out)           // (16, H, W, 3) f32
{
    __shared__ __align__(16) float seg[SEG_FLOATS];

    const int tid  = threadIdx.x;
    const int warp = tid >> 5;
    const int lane = tid & 31;
    const int q    = lane >> 2;        // quad id: 8 pixels per warp-iteration
    const int r    = lane & 3;         // slot within quad (0..2 data, 3 pad)

    const int tile_base = blockIdx.x * TILE_PX;
    const int warp_base = tile_base + warp * WARP_PX;

    // ---- 2-deep software pipeline over 16 iterations of 8 pixels ----
    int   fq[2];
    float wq[2];

    // load face id + bary weight for iteration i into stage s
    #define LOAD_IW(i, s) do {                                            \
        const int p = warp_base + (i) * 8 + q;                            \
        fq[s] = __ldcs(&pix[p]);                                          \
        wq[s] = (r < 3) ? __ldcs(&bary[p * 3 + r]) : 0.0f;                \
    } while (0)

    const float4 zero4 = make_float4(0.f, 0.f, 0.f, 0.f);

    LOAD_IW(0, 0);
    float4 v = (fq[0] >= 0) ? __ldg(&g_face_attr[fq[0]][r]) : zero4;
    LOAD_IW(1, 1);

    #pragma unroll
    for (int i = 0; i < ITERS; i++) {
        const int   s  = i & 1;
        const float4 vc = v;
        const float  wc = wq[s];

        // prefetch next gather (depends on fq loaded last iteration)
        if (i + 1 < ITERS) {
            const int fn = fq[s ^ 1];
            v = (fn >= 0) ? __ldg(&g_face_attr[fn][r]) : zero4;
        }
        // prefetch face id + weight two iterations ahead
        if (i + 2 < ITERS) LOAD_IW(i + 2, s);

        // partial contribution of this lane's vertex (lane 3: w=0 * pad)
        float sx = wc * vc.x;
        float sy = wc * vc.y;
        float sz = wc * vc.z;
        // quad reduction: all 4 lanes end with the pixel's rgb
        sx += __shfl_xor_sync(0xffffffffu, sx, 1);
        sy += __shfl_xor_sync(0xffffffffu, sy, 1);
        sz += __shfl_xor_sync(0xffffffffu, sz, 1);
        sx += __shfl_xor_sync(0xffffffffu, sx, 2);
        sy += __shfl_xor_sync(0xffffffffu, sy, 2);
        sz += __shfl_xor_sync(0xffffffffu, sz, 2);

        // lanes r=0,1,2 store one component each (contiguous, conflict-free)
        const int lp = warp * WARP_PX + i * 8 + q;   // local pixel in tile
        const float outv = (r == 0) ? sx : ((r == 1) ? sy : sz);
        if (r < 3) seg[lp * 3 + r] = outv;
    }
    #undef LOAD_IW

    __syncthreads();

    // ---- Broadcast segment to all 16 batch planes, fully coalesced ----
    const float4* s4 = reinterpret_cast<const float4*>(seg);   // 768 float4
    const float4 c0 = s4[tid];
    const float4 c1 = s4[tid + 256];
    const float4 c2 = s4[tid + 512];
    const size_t seg_base4 = (size_t)blockIdx.x * (SEG_FLOATS / 4);
    float4* o4 = reinterpret_cast<float4*>(out);
    #pragma unroll
    for (int b = 0; b < NBATCH; b++) {
        float4* dst = o4 + (size_t)b * (PLANE_FLOATS / 4) + seg_base4;
        __stcs(&dst[tid],       c0);
        __stcs(&dst[tid + 256], c1);
        __stcs(&dst[tid + 512], c2);
    }
}

extern "C" void kernel_launch(void* const* d_in, const int* in_sizes, int n_in,
                              void* d_out, int out_size)
{
    // metadata order: verts_attr (f32), face_tensor (i32), pix_to_face (i32), bary_coords (f32)
    const float* verts = (const float*)d_in[0];
    const int*   faces = (const int*)d_in[1];
    const int*   pix   = (const int*)d_in[2];
    const float* bary  = (const float*)d_in[3];
    float* out = (float*)d_out;

    build_face_attr<<<(NUM_FACES + 255) / 256, 256>>>(verts, faces);
    render_kernel<<<HW / TILE_PX, THREADS>>>(pix, bary, out);   // 1024 blocks
}

// round 10
// speedup vs baseline: 1.1333x; 1.1333x over previous
#include <cuda_runtime.h>
#include <cstdint>

// Problem constants
#define NUM_VERTS 6890
#define NUM_FACES 13776
#define IMG_H 1024
#define IMG_W 1024
#define NBATCH 16
#define HW (IMG_H * IMG_W)
#define PLANE_FLOATS (HW * 3)            // 3,145,728 floats per batch plane
#define PIX_PER_BLOCK 1024               // 256 threads x 4 pixels
#define SEG_FLOATS (PIX_PER_BLOCK * 3)   // 3072 floats = 12KB smem

// Precomputed per-face vertex attributes, 64B-aligned rows:
// row f = { v0.xyz _, v1.xyz _, v2.xyz _, pad }. 882KB -> L2-resident.
__device__ __align__(64) float4 g_face_attr[NUM_FACES][4];

// Kernel A: build the face-attr table (batch-0 vertices only; the reference's
// pixel gather never applies a per-batch face offset and batch-0 vertex
// offset is 0, so only batch 0 matters).
__global__ void __launch_bounds__(256) build_face_attr(
    const float* __restrict__ verts,   // (N, V, 3) f32
    const int*   __restrict__ faces)   // (F, 3) i32
{
    const int f = blockIdx.x * blockDim.x + threadIdx.x;
    if (f >= NUM_FACES) return;
    const int i0 = faces[f * 3 + 0];
    const int i1 = faces[f * 3 + 1];
    const int i2 = faces[f * 3 + 2];
    const float* v0 = verts + (size_t)i0 * 3;
    const float* v1 = verts + (size_t)i1 * 3;
    const float* v2 = verts + (size_t)i2 * 3;
    g_face_attr[f][0] = make_float4(v0[0], v0[1], v0[2], 0.0f);
    g_face_attr[f][1] = make_float4(v1[0], v1[1], v1[2], 0.0f);
    g_face_attr[f][2] = make_float4(v2[0], v2[1], v2[2], 0.0f);
}

// Kernel B: interpolate 4 pixels/thread into a 12KB smem segment, then
// broadcast to all 16 batch planes with coalesced float4 streaming stores.
// __launch_bounds__(256, 8): cap at 32 regs so 8 CTAs/SM are resident
// (64K regs exactly) -> double the warp supply hiding gather latency.
__global__ void __launch_bounds__(256, 8) render_kernel(
    const int*   __restrict__ pix,     // (H*W) i32
    const float* __restrict__ bary,    // (H*W, 3) f32
    float* __restrict__ out)           // (16, H, W, 3) f32
{
    __shared__ __align__(16) float seg[SEG_FLOATS];

    const int tid = threadIdx.x;
    const int p0  = blockIdx.x * PIX_PER_BLOCK + tid * 4;   // 4 pixels/thread

    // ---- Coalesced streaming input loads ----
    const float4* b4 = reinterpret_cast<const float4*>(bary + (size_t)p0 * 3);
    const float4 bA = __ldcs(&b4[0]);
    const float4 bB = __ldcs(&b4[1]);
    const float4 bC = __ldcs(&b4[2]);
    const int4 px = __ldcs(reinterpret_cast<const int4*>(pix + p0));

    const int pf[4] = { px.x, px.y, px.z, px.w };
    const float bw[4][3] = {
        { bA.x, bA.y, bA.z },
        { bA.w, bB.x, bB.y },
        { bB.z, bB.w, bC.x },
        { bC.y, bC.z, bC.w }
    };

    // ---- Compute 4 pixels; write into smem segment ----
    float* sp = seg + tid * 12;
    #pragma unroll
    for (int i = 0; i < 4; i++) {
        float r0 = 0.0f, r1 = 0.0f, r2 = 0.0f;
        const int f = pf[i];
        if (f >= 0) {
            // 3 x LDG.128 from a 64B-aligned row; table is L2-resident.
            const float4 v0 = __ldg(&g_face_attr[f][0]);
            const float4 v1 = __ldg(&g_face_attr[f][1]);
            const float4 v2 = __ldg(&g_face_attr[f][2]);
            const float w0 = bw[i][0], w1 = bw[i][1], w2 = bw[i][2];
            r0 = fmaf(w2, v2.x, fmaf(w1, v1.x, w0 * v0.x));
            r1 = fmaf(w2, v2.y, fmaf(w1, v1.y, w0 * v0.y));
            r2 = fmaf(w2, v2.z, fmaf(w1, v1.z, w0 * v0.z));
        }
        sp[i * 3 + 0] = r0;
        sp[i * 3 + 1] = r1;
        sp[i * 3 + 2] = r2;
    }
    __syncthreads();

    // ---- Broadcast segment to all 16 batch planes, fully coalesced ----
    const float4* s4 = reinterpret_cast<const float4*>(seg);   // 768 float4
    const float4 c0 = s4[tid];
    const float4 c1 = s4[tid + 256];
    const float4 c2 = s4[tid + 512];
    const size_t seg_base4 = (size_t)blockIdx.x * (SEG_FLOATS / 4);
    float4* o4 = reinterpret_cast<float4*>(out);
    #pragma unroll
    for (int b = 0; b < NBATCH; b++) {
        float4* dst = o4 + (size_t)b * (PLANE_FLOATS / 4) + seg_base4;
        __stcs(&dst[tid],       c0);
        __stcs(&dst[tid + 256], c1);
        __stcs(&dst[tid + 512], c2);
    }
}

extern "C" void kernel_launch(void* const* d_in, const int* in_sizes, int n_in,
                              void* d_out, int out_size)
{
    // metadata order: verts_attr (f32), face_tensor (i32), pix_to_face (i32), bary_coords (f32)
    const float* verts = (const float*)d_in[0];
    const int*   faces = (const int*)d_in[1];
    const int*   pix   = (const int*)d_in[2];
    const float* bary  = (const float*)d_in[3];
    float* out = (float*)d_out;

    build_face_attr<<<(NUM_FACES + 255) / 256, 256>>>(verts, faces);
    render_kernel<<<HW / PIX_PER_BLOCK, 256>>>(pix, bary, out);  // 1024 blocks
}

// round 11
// speedup vs baseline: 1.3356x; 1.1785x over previous
#include <cuda_runtime.h>
#include <cstdint>

// Problem constants
#define NUM_VERTS 6890
#define NUM_FACES 13776
#define IMG_H 1024
#define IMG_W 1024
#define NBATCH 16
#define HW (IMG_H * IMG_W)
#define PLANE_FLOATS (HW * 3)            // 3,145,728 floats per batch plane
#define THREADS 256
#define NWARPS (THREADS / 32)            // 8
#define TILE_PX 1024                     // pixels per block
#define WARP_PX 128                      // pixels per warp (lane*4)
#define WARP_FLOATS (WARP_PX * 3)        // 384 floats = 1.5KB per warp
#define SEG_FLOATS (TILE_PX * 3)         // 12KB total smem

// Precomputed per-face vertex attributes, 64B-aligned rows:
// row f = { v0.xyz _, v1.xyz _, v2.xyz _, pad }. 882KB -> L2-resident.
__device__ __align__(64) float4 g_face_attr[NUM_FACES][4];

// Kernel A: build the face-attr table (batch-0 vertices only; the reference's
// pixel gather never applies a per-batch face offset and batch-0 vertex
// offset is 0, so only batch 0 matters).
__global__ void __launch_bounds__(256) build_face_attr(
    const float* __restrict__ verts,   // (N, V, 3) f32
    const int*   __restrict__ faces)   // (F, 3) i32
{
    const int f = blockIdx.x * blockDim.x + threadIdx.x;
    if (f >= NUM_FACES) return;
    const int i0 = faces[f * 3 + 0];
    const int i1 = faces[f * 3 + 1];
    const int i2 = faces[f * 3 + 2];
    const float* v0 = verts + (size_t)i0 * 3;
    const float* v1 = verts + (size_t)i1 * 3;
    const float* v2 = verts + (size_t)i2 * 3;
    g_face_attr[f][0] = make_float4(v0[0], v0[1], v0[2], 0.0f);
    g_face_attr[f][1] = make_float4(v1[0], v1[1], v1[2], 0.0f);
    g_face_attr[f][2] = make_float4(v2[0], v2[1], v2[2], 0.0f);
}

// Kernel B: 4 pixels/thread. Each warp owns a contiguous 128-pixel (1.5KB)
// output chunk: stage in a private smem slice, __syncwarp only (no block
// barrier -> no gather/store phase convoy), then stream to all 16 batch
// planes with coalesced float4 streaming stores as soon as this warp's
// gathers have landed.
__global__ void __launch_bounds__(THREADS) render_kernel(
    const int*   __restrict__ pix,     // (H*W) i32
    const float* __restrict__ bary,    // (H*W, 3) f32
    float* __restrict__ out)           // (16, H, W, 3) f32
{
    __shared__ __align__(16) float seg[SEG_FLOATS];

    const int tid  = threadIdx.x;
    const int warp = tid >> 5;
    const int lane = tid & 31;

    const int warp_px0 = blockIdx.x * TILE_PX + warp * WARP_PX;  // warp chunk
    const int p0 = warp_px0 + lane * 4;                          // 4 px/thread

    // ---- pix first (heads the dependent gather chain), then bary ----
    const int4 px = *reinterpret_cast<const int4*>(pix + p0);
    const float4* b4 = reinterpret_cast<const float4*>(bary + (size_t)p0 * 3);
    const float4 bA = b4[0];
    const float4 bB = b4[1];
    const float4 bC = b4[2];

    const int pf[4] = { px.x, px.y, px.z, px.w };
    const float bw[4][3] = {
        { bA.x, bA.y, bA.z },
        { bA.w, bB.x, bB.y },
        { bB.z, bB.w, bC.x },
        { bC.y, bC.z, bC.w }
    };

    // ---- Compute 4 pixels into this warp's smem slice ----
    float* ws = seg + warp * WARP_FLOATS;
    float* sp = ws + lane * 12;
    #pragma unroll
    for (int i = 0; i < 4; i++) {
        float r0 = 0.0f, r1 = 0.0f, r2 = 0.0f;
        const int f = pf[i];
        if (f >= 0) {
            // 3 x LDG.128 from a 64B-aligned row; table is L2-resident.
            const float4 v0 = __ldg(&g_face_attr[f][0]);
            const float4 v1 = __ldg(&g_face_attr[f][1]);
            const float4 v2 = __ldg(&g_face_attr[f][2]);
            const float w0 = bw[i][0], w1 = bw[i][1], w2 = bw[i][2];
            r0 = fmaf(w2, v2.x, fmaf(w1, v1.x, w0 * v0.x));
            r1 = fmaf(w2, v2.y, fmaf(w1, v1.y, w0 * v0.y));
            r2 = fmaf(w2, v2.z, fmaf(w1, v1.z, w0 * v0.z));
        }
        sp[i * 3 + 0] = r0;
        sp[i * 3 + 1] = r1;
        sp[i * 3 + 2] = r2;
    }
    __syncwarp();

    // ---- Warp-local transpose read-back: 3 float4/lane, sequential ----
    const float4* ws4 = reinterpret_cast<const float4*>(ws);   // 96 float4
    const float4 c0 = ws4[lane];
    const float4 c1 = ws4[lane + 32];
    const float4 c2 = ws4[lane + 64];

    // ---- Stream this warp's 1.5KB chunk to all 16 batch planes ----
    const size_t chunk4 = (size_t)warp_px0 * 3 / 4;            // float4 index
    float4* o4 = reinterpret_cast<float4*>(out);
    #pragma unroll
    for (int b = 0; b < NBATCH; b++) {
        float4* dst = o4 + (size_t)b * (PLANE_FLOATS / 4) + chunk4;
        __stcs(&dst[lane],      c0);
        __stcs(&dst[lane + 32], c1);
        __stcs(&dst[lane + 64], c2);
    }
}

extern "C" void kernel_launch(void* const* d_in, const int* in_sizes, int n_in,
                              void* d_out, int out_size)
{
    // metadata order: verts_attr (f32), face_tensor (i32), pix_to_face (i32), bary_coords (f32)
    const float* verts = (const float*)d_in[0];
    const int*   faces = (const int*)d_in[1];
    const int*   pix   = (const int*)d_in[2];
    const float* bary  = (const float*)d_in[3];
    float* out = (float*)d_out;

    build_face_attr<<<(NUM_FACES + 255) / 256, 256>>>(verts, faces);
    render_kernel<<<HW / TILE_PX, THREADS>>>(pix, bary, out);   // 1024 blocks
}